// round 8
// baseline (speedup 1.0000x reference)
#include <cuda_runtime.h>
#include <cstdint>

#define OUT_F 16

// Monotonic ticket counter for the software global barrier. Never reset:
// each kernel execution adds exactly gridDim.x arrivals, so the counter is
// always a multiple of gridDim.x at kernel boundaries, and each CTA waits
// for the next multiple. Safe across CUDA-graph replays.
__device__ unsigned g_arrive = 0;

// ---------------------------------------------------------------------------
// Fused: zero output + global barrier + scatter-add (quad layout, 4-way ILP).
// Persistent grid of 592 CTAs (148 SMs x 4, guaranteed resident by
// __launch_bounds__(256,4)) so the software barrier cannot deadlock.
// ---------------------------------------------------------------------------
__global__ void __launch_bounds__(256, 4)
fused_zero_scatter(const int* __restrict__ src,
                   const float4* __restrict__ w,     // edge_w as [4E] float4
                   float* __restrict__ out,          // [N][16]
                   int work,                         // 4*E quad elements
                   int n4)                           // output float4 count
{
    const int tid = blockIdx.x * blockDim.x + threadIdx.x;
    const int nthreads = gridDim.x * blockDim.x;     // 151552

    // ---- phase 1: zero the output (harness poisons it with 0xAA) ----
    float4* o4 = (float4*)out;
    for (int i = tid; i < n4; i += nthreads)
        o4[i] = make_float4(0.f, 0.f, 0.f, 0.f);

    // ---- global barrier: all zero-stores visible before any RED lands ----
    __syncthreads();
    __threadfence();                                  // release our stores
    if (threadIdx.x == 0) {
        unsigned ticket = atomicAdd(&g_arrive, 1) + 1;
        unsigned target = ((ticket + gridDim.x - 1) / gridDim.x) * gridDim.x;
        while (*(volatile unsigned*)&g_arrive < target)
            __nanosleep(64);
    }
    __syncthreads();
    __threadfence();                                  // acquire peers' stores

    // ---- phase 2: scatter, 4-way unrolled grid-stride ----
    const int S = nthreads;
    int t = tid;
    for (; t + 3 * S < work; t += 4 * S) {
        int ta = t, tb = t + S, tc = t + 2 * S, td = t + 3 * S;

        // issue all 8 loads first
        int sa = __ldg(src + (ta >> 2));
        int sb = __ldg(src + (tb >> 2));
        int sc = __ldg(src + (tc >> 2));
        int sd = __ldg(src + (td >> 2));
        float4 va = __ldcs(w + ta);
        float4 vb = __ldcs(w + tb);
        float4 vc = __ldcs(w + tc);
        float4 vd = __ldcs(w + td);

        float* da = out + (size_t)sa * OUT_F + (ta & 3) * 4;
        float* db = out + (size_t)sb * OUT_F + (tb & 3) * 4;
        float* dc = out + (size_t)sc * OUT_F + (tc & 3) * 4;
        float* dd = out + (size_t)sd * OUT_F + (td & 3) * 4;
        asm volatile("red.global.add.v4.f32 [%0], {%1,%2,%3,%4};"
                     :: "l"(da), "f"(va.x), "f"(va.y), "f"(va.z), "f"(va.w) : "memory");
        asm volatile("red.global.add.v4.f32 [%0], {%1,%2,%3,%4};"
                     :: "l"(db), "f"(vb.x), "f"(vb.y), "f"(vb.z), "f"(vb.w) : "memory");
        asm volatile("red.global.add.v4.f32 [%0], {%1,%2,%3,%4};"
                     :: "l"(dc), "f"(vc.x), "f"(vc.y), "f"(vc.z), "f"(vc.w) : "memory");
        asm volatile("red.global.add.v4.f32 [%0], {%1,%2,%3,%4};"
                     :: "l"(dd), "f"(vd.x), "f"(vd.y), "f"(vd.z), "f"(vd.w) : "memory");
    }
    for (; t < work; t += S) {
        int s = __ldg(src + (t >> 2));
        float4 v = __ldcs(w + t);
        float* d = out + (size_t)s * OUT_F + (t & 3) * 4;
        asm volatile("red.global.add.v4.f32 [%0], {%1,%2,%3,%4};"
                     :: "l"(d), "f"(v.x), "f"(v.y), "f"(v.z), "f"(v.w) : "memory");
    }
}

// ---------------------------------------------------------------------------
// kernel_launch
// Inputs (metadata order): edge [2, E] int32, edge_w [E, 16] f32, N, E, F
// ---------------------------------------------------------------------------
extern "C" void kernel_launch(void* const* d_in, const int* in_sizes, int n_in,
                              void* d_out, int out_size) {
    const int*    edge   = (const int*)d_in[0];      // [2, E]; row 0 = src
    const float4* edge_w = (const float4*)d_in[1];   // [E, 16] -> [4E] float4
    float*        out    = (float*)d_out;            // [N, 16]

    const int E    = in_sizes[0] / 2;                // edge has 2*E elements
    const int work = 4 * E;                          // quad elements
    const int n4   = out_size / 4;                   // output float4 count

    const int threads = 256;
    const int blocks  = 148 * 4;                     // guaranteed co-resident

    fused_zero_scatter<<<blocks, threads>>>(edge, edge_w, out, work, n4);
}